// round 1
// baseline (speedup 1.0000x reference)
#include <cuda_runtime.h>

// LSTM_Regression: 2-layer LSTM (H=30, IN=1) + linear head, B=512, T=2048.
// One block per batch element; thread g in [0,120) owns gate g with its weight
// rows register-resident (packed f32x2). Threads 0..29 own hidden-unit state.
// Thread 120 computes the FC head off the critical path.

#define Hs 30
#define G4 120
#define Ts 2048
#define Bs 512

typedef unsigned long long ull;

__device__ __forceinline__ ull pk(float lo, float hi) {
    ull r; asm("mov.b64 %0, {%1, %2};" : "=l"(r) : "f"(lo), "f"(hi)); return r;
}
__device__ __forceinline__ void fma2(ull& d, ull a, ull b) {
    asm("fma.rn.f32x2 %0, %1, %2, %3;" : "=l"(d) : "l"(a), "l"(b), "l"(d));
}
__device__ __forceinline__ float hadd(ull a) {
    float lo, hi; asm("mov.b64 {%0, %1}, %2;" : "=f"(lo), "=f"(hi) : "l"(a)); return lo + hi;
}
__device__ __forceinline__ float ex2f(float x) { float y; asm("ex2.approx.f32 %0, %1;" : "=f"(y) : "f"(x)); return y; }
__device__ __forceinline__ float rcpf(float x) { float y; asm("rcp.approx.f32 %0, %1;" : "=f"(y) : "f"(x)); return y; }
// sigmoid(x) = 1/(1+2^(-x*log2e)); saturates correctly at +/-inf via rcp(inf)=0
__device__ __forceinline__ float sigf(float x)  { return rcpf(1.0f + ex2f(-1.4426950408889634f * x)); }
// tanh(x) = 1 - 2/(2^(2x*log2e)+1); saturates correctly (rcp(inf)=0 -> 1, ex2(-inf)=0 -> -1)
__device__ __forceinline__ float tanhf_(float x) { return 1.0f - 2.0f * rcpf(ex2f(2.8853900817779268f * x) + 1.0f); }

__global__ void __launch_bounds__(128, 4) lstm_kernel(
    const float* __restrict__ x,
    const float* __restrict__ w_ih1, const float* __restrict__ w_hh1,
    const float* __restrict__ b_ih1, const float* __restrict__ b_hh1,
    const float* __restrict__ w_ih2, const float* __restrict__ w_hh2,
    const float* __restrict__ b_ih2, const float* __restrict__ b_hh2,
    const float* __restrict__ w_fc,  const float* __restrict__ b_fc,
    float* __restrict__ out)
{
    __shared__ __align__(16) float sx[Ts];     // full x row for this batch element
    __shared__ __align__(16) float sh1[32];    // layer-1 hidden state (padded)
    __shared__ __align__(16) float sh2[32];    // layer-2 hidden state (padded)
    __shared__ __align__(16) float sg1[G4];    // layer-1 activated gates
    __shared__ __align__(16) float sg2[G4];    // layer-2 activated gates
    __shared__ __align__(16) float swfc[32];   // fc weight (padded)

    const int tid = threadIdx.x;
    const int b   = blockIdx.x;

    // Preload x row (coalesced) and init state.
    const float* xb = x + (size_t)b * Ts;
    #pragma unroll
    for (int i = 0; i < Ts / 128; i++) sx[tid + i * 128] = xb[tid + i * 128];
    if (tid < 32) {
        sh1[tid] = 0.0f;
        sh2[tid] = 0.0f;
        swfc[tid] = (tid < Hs) ? w_fc[tid] : 0.0f;
    }

    // Register-resident weights, packed as f32x2 pairs (15 pairs = 30 elems).
    ull w1p[15], w2ip[15], w2hp[15];
    float bias1 = 0.0f, bias2 = 0.0f, wx = 0.0f;
    if (tid < G4) {
        const float* r1  = w_hh1 + tid * Hs;
        const float* r2i = w_ih2 + tid * Hs;
        const float* r2h = w_hh2 + tid * Hs;
        #pragma unroll
        for (int k = 0; k < 15; k++) {
            w1p[k]  = pk(r1[2 * k],  r1[2 * k + 1]);
            w2ip[k] = pk(r2i[2 * k], r2i[2 * k + 1]);
            w2hp[k] = pk(r2h[2 * k], r2h[2 * k + 1]);
        }
        bias1 = b_ih1[tid] + b_hh1[tid];
        bias2 = b_ih2[tid] + b_hh2[tid];
        wx = w_ih1[tid];
    }
    const float bfc = b_fc[0];

    float c1 = 0.0f, c2 = 0.0f;
    float* outb = out + (size_t)b * Ts;

    const bool is_gate      = (tid < G4);
    const bool is_unit      = (tid < Hs);
    const bool is_tanh_gate = (tid >= 2 * Hs) && (tid < 3 * Hs);

    __syncthreads();

    for (int t = 0; t < Ts; t++) {
        // ---- Phase A: layer-1 gate pre-activations + nonlinearity ----
        if (is_gate) {
            const ull* h1p = (const ull*)sh1;
            ull a0 = 0ull, a1 = 0ull;
            #pragma unroll
            for (int k = 0; k < 15; k += 2) fma2(a0, w1p[k], h1p[k]);
            #pragma unroll
            for (int k = 1; k < 15; k += 2) fma2(a1, w1p[k], h1p[k]);
            float pre = fmaf(sx[t], wx, bias1) + hadd(a0) + hadd(a1);
            sg1[tid] = is_tanh_gate ? tanhf_(pre) : sigf(pre);
        }
        __syncthreads();  // B1: sg1 ready

        // ---- Phase B: layer-1 state update (threads 0..29) ----
        if (is_unit) {
            float ig = sg1[tid];
            float fg = sg1[tid + Hs];
            float gg = sg1[tid + 2 * Hs];
            float og = sg1[tid + 3 * Hs];
            c1 = fmaf(fg, c1, ig * gg);
            sh1[tid] = og * tanhf_(c1);
        }
        __syncthreads();  // B2: sh1 ready

        // ---- Phase C: layer-2 gate pre-activations; thread 120 does FC(t-1) ----
        // sh2 still holds h2[t-1] here (Phase D runs after B3), so the FC head
        // for step t-1 is computed race-free and off the critical path.
        if (is_gate) {
            const ull* h1p = (const ull*)sh1;
            const ull* h2p = (const ull*)sh2;
            ull a0 = 0ull, a1 = 0ull;
            #pragma unroll
            for (int k = 0; k < 15; k++) {
                fma2(a0, w2ip[k], h1p[k]);
                fma2(a1, w2hp[k], h2p[k]);
            }
            float pre = bias2 + hadd(a0) + hadd(a1);
            sg2[tid] = is_tanh_gate ? tanhf_(pre) : sigf(pre);
        } else if (tid == G4 && t > 0) {
            const ull* h2p = (const ull*)sh2;
            const ull* wp  = (const ull*)swfc;
            ull a0 = 0ull;
            #pragma unroll
            for (int k = 0; k < 15; k++) fma2(a0, wp[k], h2p[k]);
            outb[t - 1] = bfc + hadd(a0);
        }
        __syncthreads();  // B3: sg2 ready, FC read of sh2 complete

        // ---- Phase D: layer-2 state update (threads 0..29) ----
        // No trailing barrier: next reads of sh2 occur after next B2, and the
        // writers pass next B1 only after completing this phase.
        if (is_unit) {
            float ig = sg2[tid];
            float fg = sg2[tid + Hs];
            float gg = sg2[tid + 2 * Hs];
            float og = sg2[tid + 3 * Hs];
            c2 = fmaf(fg, c2, ig * gg);
            sh2[tid] = og * tanhf_(c2);
        }
    }

    __syncthreads();
    if (tid == G4) {
        const ull* h2p = (const ull*)sh2;
        const ull* wp  = (const ull*)swfc;
        ull a0 = 0ull;
        #pragma unroll
        for (int k = 0; k < 15; k++) fma2(a0, wp[k], h2p[k]);
        outb[Ts - 1] = bfc + hadd(a0);
    }
}

extern "C" void kernel_launch(void* const* d_in, const int* in_sizes, int n_in,
                              void* d_out, int out_size) {
    (void)in_sizes; (void)n_in; (void)out_size;
    lstm_kernel<<<Bs, 128>>>(
        (const float*)d_in[0],
        (const float*)d_in[1], (const float*)d_in[2],
        (const float*)d_in[3], (const float*)d_in[4],
        (const float*)d_in[5], (const float*)d_in[6],
        (const float*)d_in[7], (const float*)d_in[8],
        (const float*)d_in[9], (const float*)d_in[10],
        (float*)d_out);
}

// round 2
// speedup vs baseline: 1.1021x; 1.1021x over previous
#include <cuda_runtime.h>

// 2-layer LSTM (H=30, IN=1) + linear head, B=512, T=2048.
// Block = 1 batch element, 128 threads = 4 warps.
// Warp w owns gate TYPE w (0=i,1=f,2=g,3=o): lane u computes that gate for
// unit u (weight rows register-resident, f32x2 packed). Gate activations are
// exchanged via SMEM ([unit][4] layout -> LDS.128 read) with ONE barrier per
// layer. The c/h state update is computed REDUNDANTLY by every warp (bit-
// identical), so no warp ever idles waiting on a single state-owner warp.
// FC head: in-register butterfly reduction on warp 0.

#define Hs 30
#define Ts 2048
#define Bs 512

typedef unsigned long long ull;

__device__ __forceinline__ ull pk(float lo, float hi) {
    ull r; asm("mov.b64 %0, {%1, %2};" : "=l"(r) : "f"(lo), "f"(hi)); return r;
}
__device__ __forceinline__ void fma2(ull& d, ull a, ull b) {
    asm("fma.rn.f32x2 %0, %1, %2, %3;" : "=l"(d) : "l"(a), "l"(b), "l"(d));
}
__device__ __forceinline__ ull add2(ull a, ull b) {
    ull r; asm("add.rn.f32x2 %0, %1, %2;" : "=l"(r) : "l"(a), "l"(b)); return r;
}
__device__ __forceinline__ float hadd(ull a) {
    float lo, hi; asm("mov.b64 {%0, %1}, %2;" : "=f"(lo), "=f"(hi) : "l"(a)); return lo + hi;
}
__device__ __forceinline__ float ex2f(float x) { float y; asm("ex2.approx.f32 %0, %1;" : "=f"(y) : "f"(x)); return y; }
__device__ __forceinline__ float rcpf(float x) { float y; asm("rcp.approx.f32 %0, %1;" : "=f"(y) : "f"(x)); return y; }

// act(x) = aa * rcp(1 + ex2(bb*x)) + cc
//   sigmoid: aa=1, bb=-log2(e),   cc=0
//   tanh:    aa=2, bb=-2*log2(e), cc=-1   (tanh(x) = 2*sigmoid(2x) - 1)
// Saturates correctly at +/-inf (ex2(-inf)=0 -> rcp(1); ex2(+inf)=inf -> rcp=0).
__device__ __forceinline__ float act(float x, float aa, float bb, float cc) {
    return fmaf(aa, rcpf(1.0f + ex2f(bb * x)), cc);
}
// tanh for the cell state (always tanh): 1 - 2*rcp(ex2(2*log2e*x) + 1)
__device__ __forceinline__ float tanh_(float x) {
    return fmaf(-2.0f, rcpf(ex2f(2.8853900817779268f * x) + 1.0f), 1.0f);
}

__global__ void __launch_bounds__(128, 4) lstm_kernel(
    const float* __restrict__ x,
    const float* __restrict__ w_ih1, const float* __restrict__ w_hh1,
    const float* __restrict__ b_ih1, const float* __restrict__ b_hh1,
    const float* __restrict__ w_ih2, const float* __restrict__ w_hh2,
    const float* __restrict__ b_ih2, const float* __restrict__ b_hh2,
    const float* __restrict__ w_fc,  const float* __restrict__ b_fc,
    float* __restrict__ out)
{
    __shared__ __align__(16) float sx[Ts];        // x row for this batch element
    __shared__ __align__(16) float sh1w[4][32];   // per-warp private h1 copy
    __shared__ __align__(16) float sh2w[4][32];   // per-warp private h2 copy
    __shared__ __align__(16) float sg1[128];      // gates L1: [unit][4] = i,f,g,o
    __shared__ __align__(16) float sg2[128];      // gates L2: [unit][4]

    const int tid = threadIdx.x;
    const int w   = tid >> 5;   // warp = gate type (0=i,1=f,2=g,3=o)
    const int u   = tid & 31;   // lane = unit (30..31 are padding lanes)
    const int b   = blockIdx.x;

    // Preload x row, coalesced float4.
    {
        const float4* xb4 = (const float4*)(x + (size_t)b * Ts);
        float4* sx4 = (float4*)sx;
        #pragma unroll
        for (int i = 0; i < Ts / 4 / 128; i++) sx4[tid + i * 128] = xb4[tid + i * 128];
    }
    sh1w[w][u] = 0.0f;
    sh2w[w][u] = 0.0f;

    // Register-resident weight rows for gate (type w, unit u), f32x2 packed.
    const int row = w * Hs + ((u < Hs) ? u : Hs - 1);   // clamp padding lanes
    ull w1p[15], w2ip[15], w2hp[15];
    {
        const float* r1  = w_hh1 + row * Hs;
        const float* r2i = w_ih2 + row * Hs;
        const float* r2h = w_hh2 + row * Hs;
        #pragma unroll
        for (int k = 0; k < 15; k++) {
            w1p[k]  = pk(r1[2 * k],  r1[2 * k + 1]);
            w2ip[k] = pk(r2i[2 * k], r2i[2 * k + 1]);
            w2hp[k] = pk(r2h[2 * k], r2h[2 * k + 1]);
        }
    }
    const float bias1 = b_ih1[row] + b_hh1[row];
    const float bias2 = b_ih2[row] + b_hh2[row];
    const float wx    = w_ih1[row];
    const float wfc   = (u < Hs) ? w_fc[u] : 0.0f;
    const float bfc   = b_fc[0];

    // Warp-uniform activation constants (warp 2 = g gate = tanh).
    const float aa = (w == 2) ? 2.0f : 1.0f;
    const float bb = (w == 2) ? -2.8853900817779268f : -1.4426950408889634f;
    const float cc = (w == 2) ? -1.0f : 0.0f;

    float c1 = 0.0f, c2 = 0.0f;
    float* outb = out + (size_t)b * Ts;

    const ulonglong2* h1p = (const ulonglong2*)sh1w[w];
    const ulonglong2* h2p = (const ulonglong2*)sh2w[w];
    const ull* h1s = (const ull*)sh1w[w];
    const ull* h2s = (const ull*)sh2w[w];

    __syncthreads();

    #pragma unroll 1
    for (int t = 0; t < Ts; t++) {
        // ---- Gates L1: pre = bias1 + wx*x[t] + w_hh1[row] . h1 ----
        {
            ull a0 = 0ull, a1 = 0ull;
            #pragma unroll
            for (int k = 0; k < 7; k++) {
                ulonglong2 v = h1p[k];
                fma2(a0, w1p[2 * k],     v.x);
                fma2(a1, w1p[2 * k + 1], v.y);
            }
            fma2(a0, w1p[14], h1s[14]);
            float pre = fmaf(sx[t], wx, bias1) + hadd(add2(a0, a1));
            sg1[4 * u + w] = act(pre, aa, bb, cc);
        }
        __syncthreads();   // B1: sg1 ready

        // ---- State L1 (redundant in every warp) ----
        {
            float4 g = *(const float4*)(sg1 + 4 * u);   // i,f,gg,o
            c1 = fmaf(g.y, c1, g.x * g.z);
            sh1w[w][u] = g.w * tanh_(c1);
        }
        __syncwarp();      // own-warp STS(h1) -> LDS(h1) ordering

        // ---- Gates L2: pre = bias2 + w_ih2[row] . h1 + w_hh2[row] . h2 ----
        // (h2 written last step; ordered by B1 this step)
        {
            ull a0 = 0ull, a1 = 0ull, a2 = 0ull, a3 = 0ull;
            #pragma unroll
            for (int k = 0; k < 7; k++) {
                ulonglong2 v1 = h1p[k];
                ulonglong2 v2 = h2p[k];
                fma2(a0, w2ip[2 * k],     v1.x);
                fma2(a1, w2ip[2 * k + 1], v1.y);
                fma2(a2, w2hp[2 * k],     v2.x);
                fma2(a3, w2hp[2 * k + 1], v2.y);
            }
            fma2(a0, w2ip[14], h1s[14]);
            fma2(a2, w2hp[14], h2s[14]);
            float pre = bias2 + hadd(add2(add2(a0, a1), add2(a2, a3)));
            sg2[4 * u + w] = act(pre, aa, bb, cc);
        }
        __syncthreads();   // B2: sg2 ready

        // ---- State L2 (redundant) + FC head ----
        {
            float4 g = *(const float4*)(sg2 + 4 * u);
            c2 = fmaf(g.y, c2, g.x * g.z);
            float h2v = g.w * tanh_(c2);
            sh2w[w][u] = h2v;
            if (w == 0) {
                float p = (u < Hs) ? wfc * h2v : 0.0f;
                #pragma unroll
                for (int s = 16; s; s >>= 1) p += __shfl_xor_sync(0xffffffffu, p, s);
                if (u == 0) outb[t] = p + bfc;
            }
        }
        // No trailing barrier: next-step gates L1 reads only sh1w (own-warp,
        // synced); next-step gates L2 reads sh2w after next B1 (syncthreads).
    }
}

extern "C" void kernel_launch(void* const* d_in, const int* in_sizes, int n_in,
                              void* d_out, int out_size) {
    (void)in_sizes; (void)n_in; (void)out_size;
    lstm_kernel<<<Bs, 128>>>(
        (const float*)d_in[0],
        (const float*)d_in[1], (const float*)d_in[2],
        (const float*)d_in[3], (const float*)d_in[4],
        (const float*)d_in[5], (const float*)d_in[6],
        (const float*)d_in[7], (const float*)d_in[8],
        (const float*)d_in[9], (const float*)d_in[10],
        (float*)d_out);
}

// round 3
// speedup vs baseline: 1.2321x; 1.1179x over previous
#include <cuda_runtime.h>

// 2-layer LSTM (H=30, IN=1) + linear head, B=512, T=2048.
// Block = 1 batch element, 128 threads = 4 warps; warp w owns gate TYPE w
// (0=i,1=f,2=g,3=o), lane u owns unit u. Weight rows register-resident (f32x2).
//
// SOFTWARE PIPELINE across layers: iteration t computes L1 gates for step t
// and L2 gates for step t-1 in the SAME phase (both need only h1[t-1] and
// h2[t-2]) -> ONE __syncthreads per step. Gate buffers are double-buffered
// so next iteration's gate writes can't race this iteration's state reads.
// c/h state updates are computed redundantly per warp (warp-private h copies,
// own-warp STS->LDS ordered by __syncwarp). FC head: shfl reduce on warp 0.

#define Hs 30
#define Ts 2048
#define Bs 512

typedef unsigned long long ull;

__device__ __forceinline__ ull pk(float lo, float hi) {
    ull r; asm("mov.b64 %0, {%1, %2};" : "=l"(r) : "f"(lo), "f"(hi)); return r;
}
__device__ __forceinline__ void fma2(ull& d, ull a, ull b) {
    asm("fma.rn.f32x2 %0, %1, %2, %3;" : "=l"(d) : "l"(a), "l"(b), "l"(d));
}
__device__ __forceinline__ ull add2(ull a, ull b) {
    ull r; asm("add.rn.f32x2 %0, %1, %2;" : "=l"(r) : "l"(a), "l"(b)); return r;
}
__device__ __forceinline__ float hadd(ull a) {
    float lo, hi; asm("mov.b64 {%0, %1}, %2;" : "=f"(lo), "=f"(hi) : "l"(a)); return lo + hi;
}
__device__ __forceinline__ float ex2f(float x) { float y; asm("ex2.approx.f32 %0, %1;" : "=f"(y) : "f"(x)); return y; }
__device__ __forceinline__ float rcpf(float x) { float y; asm("rcp.approx.f32 %0, %1;" : "=f"(y) : "f"(x)); return y; }

// act(x) = aa * rcp(1 + ex2(bb*x)) + cc   (sigmoid or tanh by constants)
__device__ __forceinline__ float act(float x, float aa, float bb, float cc) {
    return fmaf(aa, rcpf(1.0f + ex2f(bb * x)), cc);
}
__device__ __forceinline__ float tanh_(float x) {
    return fmaf(-2.0f, rcpf(ex2f(2.8853900817779268f * x) + 1.0f), 1.0f);
}

__global__ void __launch_bounds__(128, 4) lstm_kernel(
    const float* __restrict__ x,
    const float* __restrict__ w_ih1, const float* __restrict__ w_hh1,
    const float* __restrict__ b_ih1, const float* __restrict__ b_hh1,
    const float* __restrict__ w_ih2, const float* __restrict__ w_hh2,
    const float* __restrict__ b_ih2, const float* __restrict__ b_hh2,
    const float* __restrict__ w_fc,  const float* __restrict__ b_fc,
    float* __restrict__ out)
{
    __shared__ __align__(16) float sx[Ts];        // x row for this batch element
    __shared__ __align__(16) float sh1w[4][32];   // per-warp private h1 copy
    __shared__ __align__(16) float sh2w[4][32];   // per-warp private h2 copy
    __shared__ __align__(16) float sg[2][2][128]; // [buf][layer][unit*4+gate]

    const int tid = threadIdx.x;
    const int w   = tid >> 5;   // warp = gate type
    const int u   = tid & 31;   // lane = unit (30,31 padding)
    const int b   = blockIdx.x;

    {   // coalesced x preload
        const float4* xb4 = (const float4*)(x + (size_t)b * Ts);
        float4* sx4 = (float4*)sx;
        #pragma unroll
        for (int i = 0; i < Ts / 4 / 128; i++) sx4[tid + i * 128] = xb4[tid + i * 128];
    }
    sh1w[w][u] = 0.0f;
    sh2w[w][u] = 0.0f;

    const int row = w * Hs + ((u < Hs) ? u : Hs - 1);
    ull w1p[15], w2ip[15], w2hp[15];
    {
        const float* r1  = w_hh1 + row * Hs;
        const float* r2i = w_ih2 + row * Hs;
        const float* r2h = w_hh2 + row * Hs;
        #pragma unroll
        for (int k = 0; k < 15; k++) {
            w1p[k]  = pk(r1[2 * k],  r1[2 * k + 1]);
            w2ip[k] = pk(r2i[2 * k], r2i[2 * k + 1]);
            w2hp[k] = pk(r2h[2 * k], r2h[2 * k + 1]);
        }
    }
    const float bias1 = b_ih1[row] + b_hh1[row];
    const float bias2 = b_ih2[row] + b_hh2[row];
    const float wx    = w_ih1[row];
    const float wfc   = (u < Hs) ? w_fc[u] : 0.0f;
    const float bfc   = b_fc[0];

    // warp-uniform activation constants (warp 2 = g gate = tanh)
    const float aa = (w == 2) ? 2.0f : 1.0f;
    const float bb = (w == 2) ? -2.8853900817779268f : -1.4426950408889634f;
    const float cc = (w == 2) ? -1.0f : 0.0f;

    float c1 = 0.0f, c2 = 0.0f;
    float* outb = out + (size_t)b * Ts;

    const ulonglong2* h1p = (const ulonglong2*)sh1w[w];
    const ulonglong2* h2p = (const ulonglong2*)sh2w[w];
    const ull* h1s = (const ull*)sh1w[w];
    const ull* h2s = (const ull*)sh2w[w];

    __syncthreads();

    // Pipelined loop: iteration t handles L1 gates/state for step t and
    // L2 gates/state (+ output) for step t-1. Ts+1 iterations total.
    #pragma unroll 1
    for (int t = 0; t <= Ts; t++) {
        float* sgb = &sg[t & 1][0][0];     // this iteration's gate buffer
        const bool doL1 = (t < Ts);
        const bool doL2 = (t > 0);

        // ---- Fused gate phase ----
        {
            ull a0 = 0ull, a1 = 0ull;      // L1: w_hh1 . h1[t-1]
            ull e0 = 0ull, e1 = 0ull;      // L2: w_ih2 . h1[t-1]  (same h1 loads)
            ull d0 = 0ull, d1 = 0ull;      // L2: w_hh2 . h2[t-2]
            #pragma unroll
            for (int k = 0; k < 7; k++) {
                ulonglong2 v1 = h1p[k];
                ulonglong2 v2 = h2p[k];
                fma2(a0, w1p[2 * k],      v1.x);
                fma2(a1, w1p[2 * k + 1],  v1.y);
                fma2(e0, w2ip[2 * k],     v1.x);
                fma2(e1, w2ip[2 * k + 1], v1.y);
                fma2(d0, w2hp[2 * k],     v2.x);
                fma2(d1, w2hp[2 * k + 1], v2.y);
            }
            {
                ull v1t = h1s[14], v2t = h2s[14];
                fma2(a0, w1p[14],  v1t);
                fma2(e0, w2ip[14], v1t);
                fma2(d0, w2hp[14], v2t);
            }
            if (doL1) {
                float pre1 = fmaf(sx[t], wx, bias1) + hadd(add2(a0, a1));
                sgb[4 * u + w] = act(pre1, aa, bb, cc);
            }
            if (doL2) {
                float pre2 = bias2 + hadd(add2(add2(e0, e1), add2(d0, d1)));
                sgb[128 + 4 * u + w] = act(pre2, aa, bb, cc);
            }
        }
        __syncthreads();   // gates ready (single barrier per step)

        // ---- Fused state phase (redundant per warp) ----
        if (doL1) {
            float4 g = *(const float4*)(sgb + 4 * u);       // i,f,g,o for L1[t]
            c1 = fmaf(g.y, c1, g.x * g.z);
            sh1w[w][u] = g.w * tanh_(c1);
        }
        if (doL2) {
            float4 g = *(const float4*)(sgb + 128 + 4 * u); // i,f,g,o for L2[t-1]
            c2 = fmaf(g.y, c2, g.x * g.z);
            float h2v = g.w * tanh_(c2);
            sh2w[w][u] = h2v;
            if (w == 0) {
                float p = wfc * h2v;    // wfc = 0 on padding lanes
                #pragma unroll
                for (int s = 16; s; s >>= 1) p += __shfl_xor_sync(0xffffffffu, p, s);
                if (u == 0) outb[t - 1] = p + bfc;
            }
        }
        __syncwarp();      // own-warp STS(h) -> next-iter LDS(h) ordering
        // No second syncthreads: next iteration writes gate buffer (t+1)&1,
        // while this iteration's reads were from buffer t&1; cross-warp
        // reuse of a buffer is separated by the next iteration's barrier.
    }
}

extern "C" void kernel_launch(void* const* d_in, const int* in_sizes, int n_in,
                              void* d_out, int out_size) {
    (void)in_sizes; (void)n_in; (void)out_size;
    lstm_kernel<<<Bs, 128>>>(
        (const float*)d_in[0],
        (const float*)d_in[1], (const float*)d_in[2],
        (const float*)d_in[3], (const float*)d_in[4],
        (const float*)d_in[5], (const float*)d_in[6],
        (const float*)d_in[7], (const float*)d_in[8],
        (const float*)d_in[9], (const float*)d_in[10],
        (float*)d_out);
}